// round 6
// baseline (speedup 1.0000x reference)
#include <cuda_runtime.h>

// ClosebyValuationFunction:
//   out[i] = (|z1[i,4]-z2[i,4]| < 2.0 && |z1[i,5]-z2[i,5]| <= 0.1) ? 0.99 : 0.01
//
// Strategy: SMEM-staged streaming. Each block copies a contiguous 1024-row
// (24 KB) chunk of each input into shared memory with perfectly coalesced
// LDG.128 (4 sectors / 4 wavefronts per warp request — R4's strided gather
// cost ~24 wavefronts per request and regressed), then extracts columns
// 4/5 from SMEM and writes one coalesced float4 of outputs per thread.
// DRAM traffic is the irreducible 436 MB either way; this maximizes
// request-stream efficiency.

constexpr int BLOCK    = 256;
constexpr int ROWS_PB  = 1024;                 // rows per block
constexpr int F_PB     = ROWS_PB * 6;          // floats per input per block (6144)
constexpr int F4_PB    = F_PB / 4;             // float4 per input per block (1536)
constexpr int F4_PT    = F4_PB / BLOCK;        // float4 per thread per input (6)

__global__ __launch_bounds__(BLOCK)
void closeby_stage_kernel(const float4* __restrict__ z1,
                          const float4* __restrict__ z2,
                          float4* __restrict__ out)
{
    __shared__ float s1[F_PB];
    __shared__ float s2[F_PB];

    const int  tid  = threadIdx.x;
    const long base = (long)blockIdx.x * F4_PB;

    float4* s1v = reinterpret_cast<float4*>(s1);
    float4* s2v = reinterpret_cast<float4*>(s2);

#pragma unroll
    for (int i = 0; i < F4_PT; i++)
        s1v[i * BLOCK + tid] = __ldcs(&z1[base + i * BLOCK + tid]);
#pragma unroll
    for (int i = 0; i < F4_PT; i++)
        s2v[i * BLOCK + tid] = __ldcs(&z2[base + i * BLOCK + tid]);

    __syncthreads();

    // Thread tid computes rows 4*tid .. 4*tid+3 of this block's chunk.
    float4 r;
    float* rp = &r.x;
#pragma unroll
    for (int j = 0; j < 4; j++) {
        int idx = 6 * (4 * tid + j) + 4;                       // col4 offset (even)
        float2 a = *reinterpret_cast<const float2*>(&s1[idx]);
        float2 b = *reinterpret_cast<const float2*>(&s2[idx]);
        bool close = (fabsf(a.x - b.x) < 2.0f) & (fabsf(a.y - b.y) <= 0.1f);
        rp[j] = close ? 0.99f : 0.01f;
    }

    out[(long)blockIdx.x * (ROWS_PB / 4) + tid] = r;
}

// Tail: rows not covered by full 1024-row blocks (none for n = 2^23).
__global__ void closeby_tail_kernel(const float2* __restrict__ z1,
                                    const float2* __restrict__ z2,
                                    float* __restrict__ out,
                                    int start, int n)
{
    int i = start + blockIdx.x * blockDim.x + threadIdx.x;
    if (i < n) {
        int idx = 3 * i + 2;                // float2 index of (col4, col5)
        float2 a = __ldg(&z1[idx]);
        float2 b = __ldg(&z2[idx]);
        bool close = (fabsf(a.x - b.x) < 2.0f) & (fabsf(a.y - b.y) <= 0.1f);
        out[i] = close ? 0.99f : 0.01f;
    }
}

extern "C" void kernel_launch(void* const* d_in, const int* in_sizes, int n_in,
                              void* d_out, int out_size)
{
    int n = out_size;                        // B rows (= in_sizes[0] / 6)
    int full_blocks = n / ROWS_PB;

    if (full_blocks > 0) {
        closeby_stage_kernel<<<full_blocks, BLOCK>>>(
            (const float4*)d_in[0], (const float4*)d_in[1], (float4*)d_out);
    }
    int tail_start = full_blocks * ROWS_PB;
    int tail = n - tail_start;
    if (tail > 0) {
        int tb = (tail + 255) / 256;
        closeby_tail_kernel<<<tb, 256>>>(
            (const float2*)d_in[0], (const float2*)d_in[1],
            (float*)d_out, tail_start, n);
    }
}

// round 7
// speedup vs baseline: 1.0988x; 1.0988x over previous
#include <cuda_runtime.h>

// ClosebyValuationFunction:
//   out[i] = (|z1[i,4]-z2[i,4]| < 2.0 && |z1[i,5]-z2[i,5]| <= 0.1) ? 0.99 : 0.01
//
// R2 structure (best measured: DRAM 83.5%, 6828 GB/s): one row per thread,
// gathered float2 of (col4,col5) at float2 index 3i+2. Every 32 B sector of
// both inputs is needed (lcm(24,32)=96 B period → 3/3 sectors touched), so
// traffic is at the 436 MB floor; measurements across R2/R4/R6 show the
// binding limit is the chip LTS throughput cap (~6.8 TB/s), which this
// pattern already saturates. R6 change: evict-first streaming hints
// (__ldcs/__stcs) — 402 MB of zero-reuse data shouldn't displace L2.

__global__ __launch_bounds__(256)
void closeby_kernel(const float2* __restrict__ z1,
                    const float2* __restrict__ z2,
                    float* __restrict__ out,
                    int n)
{
    int i = blockIdx.x * blockDim.x + threadIdx.x;
    if (i < n) {
        int idx = 3 * i + 2;            // float2 index of (col4, col5) in row i
        float2 a = __ldcs(&z1[idx]);
        float2 b = __ldcs(&z2[idx]);
        float dx = fabsf(a.x - b.x);
        float dy = fabsf(a.y - b.y);
        bool close = (dx < 2.0f) & (dy <= 0.1f);
        __stcs(&out[i], close ? 0.99f : 0.01f);
    }
}

extern "C" void kernel_launch(void* const* d_in, const int* in_sizes, int n_in,
                              void* d_out, int out_size)
{
    const float2* z1 = (const float2*)d_in[0];
    const float2* z2 = (const float2*)d_in[1];
    float* out = (float*)d_out;
    int n = out_size;                   // B rows (= in_sizes[0] / 6)

    int threads = 256;
    int blocks = (n + threads - 1) / threads;
    closeby_kernel<<<blocks, threads>>>(z1, z2, out, n);
}